// round 3
// baseline (speedup 1.0000x reference)
#include <cuda_runtime.h>
#include <cuda_bf16.h>
#include <math.h>

#define NB 8
#define LL 4096
#define HH 8
#define DD 64
#define HT 64
#define WD 64
#define NHH (NB*HH)          // 64
#define CHUNKS 16
#define CROWS (LL/CHUNKS)    // 256
#define ROWSTRIDE (HH*DD)    // 512
#define TILE_L 128
#define TY 16

typedef unsigned long long ull;

// ---------------- device scratch ----------------
__device__ float g_kvp[CHUNKS][NHH][DD][DD];
__device__ float g_ksp[CHUNKS][NHH][DD];
__device__ float g_kv[NHH][DD][DD];
__device__ float g_ksum[NHH][DD];

// ---------------- f32x2 helpers ----------------
__device__ __forceinline__ void ffma2(ull& d, ull a, ull b){
    asm("fma.rn.f32x2 %0, %1, %2, %0;" : "+l"(d) : "l"(a), "l"(b));
}
__device__ __forceinline__ ull pack2(float lo, float hi){
    ull r; asm("mov.b64 %0, {%1, %2};" : "=l"(r) : "f"(lo), "f"(hi)); return r;
}
__device__ __forceinline__ void unpack2(ull v, float& lo, float& hi){
    asm("mov.b64 {%0, %1}, %2;" : "=f"(lo), "=f"(hi) : "l"(v));
}
__device__ __forceinline__ void fadd2(ull& d, ull a){
    asm("add.rn.f32x2 %0, %0, %1;" : "+l"(d) : "l"(a));
}
__device__ __forceinline__ void f4add(float4& a, const float4 b){
    a.x += b.x; a.y += b.y; a.z += b.z; a.w += b.w;
}
__device__ __forceinline__ float softinv(float p){
    float s = (p > 20.f) ? p : log1pf(expf(p));
    return 1.f / s;
}

// ---------------- K1: kv & ksum partials — smem-tiled GEMM ----------------
// 64 threads. Stages of 64 rows. a = k' pairs (d-lanes), b = v duplicated.
// kt4: [64 rows][16 float4], XOR-swizzled (i ^ (row&15)).
// vt:  [64 rows][65 ull], element j at phys(j)=(j&7)*8+(j>>3), value (v,v).
#define KV_SMEM (16384 + 64*65*8 + 256)
__global__ void __launch_bounds__(64) k_kv(const float* __restrict__ keys,
                                           const float* __restrict__ values,
                                           const float* __restrict__ sp){
    extern __shared__ char smemraw[];
    float4* kt4  = (float4*)smemraw;                 // 16384 B
    ull*    vt   = (ull*)(smemraw + 16384);          // 33280 B
    float*  invs = (float*)(smemraw + 16384 + 33280);

    const int nh    = blockIdx.x & (NHH-1);
    const int chunk = blockIdx.x >> 6;
    const int n = nh >> 3, h = nh & 7;
    const int t = threadIdx.x, td = t >> 3, tj = t & 7;

    invs[t] = softinv(sp[t]);
    __syncthreads();

    const size_t base = ((size_t)(n*LL + chunk*CROWS)*HH + h)*DD;

    ull acc[4][8];
    #pragma unroll
    for (int a = 0; a < 4; ++a)
        #pragma unroll
        for (int b = 0; b < 8; ++b) acc[a][b] = 0ull;
    float ksum_r = 0.f;

    for (int stage = 0; stage < CROWS/64; ++stage){
        __syncthreads();   // previous tiles fully consumed
        {   // transform row (stage*64 + t); stage k' and dup-v
            const int r = stage*64 + t;
            const float4* kp = (const float4*)(keys   + base + (size_t)r*ROWSTRIDE);
            const float4* vp = (const float4*)(values + base + (size_t)r*ROWSTRIDE);
            ull* vrow = vt + t*65;
            float4 c[16];
            float s2 = 0.f, s6 = 0.f;
            #pragma unroll
            for (int i = 0; i < 16; ++i){
                float4 k4 = kp[i], v4 = vp[i];
                float4 iv = ((const float4*)invs)[i];
                float4 x, cc;
                x.x = (fmaxf(k4.x,0.f)+1e-6f)*iv.x;
                x.y = (fmaxf(k4.y,0.f)+1e-6f)*iv.y;
                x.z = (fmaxf(k4.z,0.f)+1e-6f)*iv.z;
                x.w = (fmaxf(k4.w,0.f)+1e-6f)*iv.w;
                cc.x = x.x*x.x*x.x; cc.y = x.y*x.y*x.y;
                cc.z = x.z*x.z*x.z; cc.w = x.w*x.w*x.w;
                s2 += x.x*x.x + x.y*x.y + x.z*x.z + x.w*x.w;
                s6 += cc.x*cc.x + cc.y*cc.y + cc.z*cc.z + cc.w*cc.w;
                c[i] = cc;
                // dup-v writes, j = 4i+e, phys(j) compile-time
                vrow[(((4*i+0)&7)<<3) + ((4*i+0)>>3)] = pack2(v4.x, v4.x);
                vrow[(((4*i+1)&7)<<3) + ((4*i+1)>>3)] = pack2(v4.y, v4.y);
                vrow[(((4*i+2)&7)<<3) + ((4*i+2)>>3)] = pack2(v4.z, v4.z);
                vrow[(((4*i+3)&7)<<3) + ((4*i+3)>>3)] = pack2(v4.w, v4.w);
            }
            const float rt = sqrtf(s2/s6);
            const int swb = t & 15;
            #pragma unroll
            for (int i = 0; i < 16; ++i){
                float4 cc = c[i];
                cc.x *= rt; cc.y *= rt; cc.z *= rt; cc.w *= rt;
                kt4[t*16 + (i ^ swb)] = cc;
            }
        }
        __syncthreads();

        // ksum: column sweep (thread t sums k'[.][t])
        {
            float ksl = 0.f;
            const int g = t >> 2, e = t & 3;
            #pragma unroll 8
            for (int r = 0; r < 64; ++r)
                ksl += ((const float*)&kt4[r*16 + (g ^ (r&15))])[e];
            ksum_r += ksl;
        }

        // GEMM over 64 staged rows
        #pragma unroll 4
        for (int r2 = 0; r2 < 64; ++r2){
            const int sw = r2 & 15;
            const ulonglong2 A0 = *(const ulonglong2*)&kt4[r2*16 + ((td*2  ) ^ sw)];
            const ulonglong2 A1 = *(const ulonglong2*)&kt4[r2*16 + ((td*2+1) ^ sw)];
            const ull* bp = vt + r2*65 + tj;
            ull b[8];
            #pragma unroll
            for (int c = 0; c < 8; ++c) b[c] = bp[c*8];
            #pragma unroll
            for (int c = 0; c < 8; ++c){
                ffma2(acc[0][c], A0.x, b[c]);
                ffma2(acc[1][c], A0.y, b[c]);
                ffma2(acc[2][c], A1.x, b[c]);
                ffma2(acc[3][c], A1.y, b[c]);
            }
        }
    }

    // epilogue: unpack f32x2 (d_even,d_odd) lanes into row-major float4 stores
    #pragma unroll
    for (int dp = 0; dp < 4; ++dp){
        float lo[8], hi[8];
        #pragma unroll
        for (int c = 0; c < 8; ++c) unpack2(acc[dp][c], lo[c], hi[c]);
        float4* re = (float4*)&g_kvp[chunk][nh][td*8 + dp*2    ][tj*8];
        float4* ro = (float4*)&g_kvp[chunk][nh][td*8 + dp*2 + 1][tj*8];
        re[0] = make_float4(lo[0],lo[1],lo[2],lo[3]);
        re[1] = make_float4(lo[4],lo[5],lo[6],lo[7]);
        ro[0] = make_float4(hi[0],hi[1],hi[2],hi[3]);
        ro[1] = make_float4(hi[4],hi[5],hi[6],hi[7]);
    }
    g_ksp[chunk][nh][t] = ksum_r;
}

// ---------------- K1b: parallel deterministic chunk reduction ----------------
__global__ void __launch_bounds__(128) k_kvreduce(){
    const int gid = blockIdx.x*128 + threadIdx.x;   // 65536 float4 outputs
    const float4* src = (const float4*)g_kvp;
    float4 s = make_float4(0,0,0,0);
    #pragma unroll
    for (int c = 0; c < CHUNKS; ++c) f4add(s, src[(size_t)c*65536 + gid]);
    ((float4*)g_kv)[gid] = s;
    if (gid < NHH*DD){
        const float* ks = (const float*)g_ksp;
        float acc = 0.f;
        #pragma unroll
        for (int c = 0; c < CHUNKS; ++c) acc += ks[c*NHH*DD + gid];
        ((float*)g_ksum)[gid] = acc;
    }
}

// ---------------- K2: attention GEMM (RMW add onto conv output) ----------------
// kvd: [64 d][65 ull] duplicated (kv,kv), j at phys(j).
// qt:  [64 d][128] floats, group-swizzled: logical group g stored at g^(d&31).
#define ATTN_SMEM (64*65*8 + 64*128*4 + 256 + 256)
__global__ void __launch_bounds__(128) k_attn(const float* __restrict__ qin,
                                              const float* __restrict__ sp,
                                              float* __restrict__ out){
    extern __shared__ char smemraw[];
    ull*   kvd    = (ull*)smemraw;                        // 33280
    float* qt     = (float*)(smemraw + 33280);            // 32768
    float* ksum_s = (float*)(smemraw + 33280 + 32768);    // 256
    float* invs   = (float*)(smemraw + 33280 + 32768 + 256);

    const int lt = blockIdx.x & 31;
    const int nh = (NHH-1) - (blockIdx.x >> 5);   // descending: L2 reuse of conv writes
    const int n = nh >> 3, h = nh & 7;
    const int t = threadIdx.x;
    const int tr = t >> 3, tc = t & 7;

    {   // load kv duplicated: thread t -> d = t>>1, j-half = (t&1)*32
        const int d = t >> 1, jh = (t & 1)*32;
        const float4* src = (const float4*)&g_kv[nh][d][jh];
        ull* dst = kvd + d*65 + (t&1)*4;
        #pragma unroll
        for (int i = 0; i < 8; ++i){
            float4 v = src[i];
            dst[(((4*i+0)&7)<<3) + ((4*i+0)>>3)] = pack2(v.x, v.x);
            dst[(((4*i+1)&7)<<3) + ((4*i+1)>>3)] = pack2(v.y, v.y);
            dst[(((4*i+2)&7)<<3) + ((4*i+2)>>3)] = pack2(v.z, v.z);
            dst[(((4*i+3)&7)<<3) + ((4*i+3)>>3)] = pack2(v.w, v.w);
        }
        if (t < DD){ ksum_s[t] = g_ksum[nh][t]; invs[t] = softinv(sp[t]); }
    }
    __syncthreads();

    const size_t base = ((size_t)(n*LL + lt*TILE_L)*HH + h)*DD;

    {   // transform row t; write qt swizzled (conflict-free column stores)
        const float4* qp = (const float4*)(qin + base + (size_t)t*ROWSTRIDE);
        float4 c[16];
        float s2 = 0.f, s6 = 0.f, sd = 0.f;
        #pragma unroll
        for (int i = 0; i < 16; ++i){
            float4 q4 = qp[i];
            float4 iv = ((const float4*)invs)[i];
            float4 ks = ((const float4*)ksum_s)[i];
            float4 x, cc;
            x.x = (fmaxf(q4.x,0.f)+1e-6f)*iv.x;
            x.y = (fmaxf(q4.y,0.f)+1e-6f)*iv.y;
            x.z = (fmaxf(q4.z,0.f)+1e-6f)*iv.z;
            x.w = (fmaxf(q4.w,0.f)+1e-6f)*iv.w;
            cc.x = x.x*x.x*x.x; cc.y = x.y*x.y*x.y;
            cc.z = x.z*x.z*x.z; cc.w = x.w*x.w*x.w;
            s2 += x.x*x.x + x.y*x.y + x.z*x.z + x.w*x.w;
            s6 += cc.x*cc.x + cc.y*cc.y + cc.z*cc.z + cc.w*cc.w;
            sd += cc.x*ks.x + cc.y*ks.y + cc.z*ks.z + cc.w*ks.w;
            c[i] = cc;
        }
        const float rt = sqrtf(s2/s6);
        const float z  = 1.f / (rt*sd + 1e-6f);
        const float m  = rt * z;
        const int g = t >> 2, e = t & 3;
        #pragma unroll
        for (int i = 0; i < 16; ++i){
            qt[(4*i+0)*128 + ((g ^ ((4*i+0)&31))<<2) + e] = c[i].x * m;
            qt[(4*i+1)*128 + ((g ^ ((4*i+1)&31))<<2) + e] = c[i].y * m;
            qt[(4*i+2)*128 + ((g ^ ((4*i+2)&31))<<2) + e] = c[i].z * m;
            qt[(4*i+3)*128 + ((g ^ ((4*i+3)&31))<<2) + e] = c[i].w * m;
        }
    }
    __syncthreads();

    // GEMM: thread = 8 rows (4 f32x2 row-pairs) x 8 cols
    ull acc[4][8];
    #pragma unroll
    for (int a = 0; a < 4; ++a)
        #pragma unroll
        for (int b = 0; b < 8; ++b) acc[a][b] = 0ull;

    const int g0 = 2*tr;
    #pragma unroll 4
    for (int d = 0; d < DD; ++d){
        const float* arow = qt + d*128;
        const int k = d & 31;
        const ulonglong2 A0 = *(const ulonglong2*)(arow + (((g0  ) ^ k)<<2));
        const ulonglong2 A1 = *(const ulonglong2*)(arow + (((g0+1) ^ k)<<2));
        const ull* bp = kvd + d*65 + tc;
        ull b[8];
        #pragma unroll
        for (int c = 0; c < 8; ++c) b[c] = bp[c*8];
        #pragma unroll
        for (int c = 0; c < 8; ++c){
            ffma2(acc[0][c], A0.x, b[c]);
            ffma2(acc[1][c], A0.y, b[c]);
            ffma2(acc[2][c], A1.x, b[c]);
            ffma2(acc[3][c], A1.y, b[c]);
        }
    }

    // RMW epilogue: out holds conv(v)+bias
    float* ob = out + base + (size_t)(tr*8)*ROWSTRIDE + tc*8;
    #pragma unroll
    for (int rp = 0; rp < 4; ++rp){
        float lo[8], hi[8];
        #pragma unroll
        for (int c = 0; c < 8; ++c) unpack2(acc[rp][c], lo[c], hi[c]);
        float4* pe = (float4*)(ob + (size_t)(2*rp  )*ROWSTRIDE);
        float4* po = (float4*)(ob + (size_t)(2*rp+1)*ROWSTRIDE);
        float4 e0 = pe[0], e1 = pe[1], o0 = po[0], o1 = po[1];
        pe[0] = make_float4(e0.x+lo[0], e0.y+lo[1], e0.z+lo[2], e0.w+lo[3]);
        pe[1] = make_float4(e1.x+lo[4], e1.y+lo[5], e1.z+lo[6], e1.w+lo[7]);
        po[0] = make_float4(o0.x+hi[0], o0.y+hi[1], o0.z+hi[2], o0.w+hi[3]);
        po[1] = make_float4(o1.x+hi[4], o1.y+hi[5], o1.z+hi[6], o1.w+hi[7]);
    }
}

// ---------------- K3: depthwise 5x5 conv, out = conv(v) + bias ----------------
#define K3_SMEM_FLOATS (5*68*64 + 25*64)
__global__ void __launch_bounds__(256,2) k_conv(const float* __restrict__ vin,
                                                const float* __restrict__ wt,
                                                const float* __restrict__ bias,
                                                float* __restrict__ out){
    extern __shared__ float sm[];
    float* ring = sm;                 // 5*68*64
    float* wsh  = sm + 5*68*64;       // 25*64

    const int yt = blockIdx.x & 3;
    const int nh = blockIdx.x >> 2;
    const int n = nh >> 3, h = nh & 7;
    const int t = threadIdx.x;
    const int dp = t & 31;
    const int xg = t >> 5;

    for (int i = t; i < 25*DD; i += 256){
        int tap = i >> 6, d = i & 63;
        wsh[i] = wt[d*25 + tap];
    }
    {
        int xi = t >> 6;
        int d  = t & 63;
        int xp = (xi < 2) ? xi : (64 + xi);
        #pragma unroll
        for (int s = 0; s < 5; ++s) ring[(s*68 + xp)*64 + d] = 0.f;
    }
    __syncthreads();

    ull wr[25];
    #pragma unroll
    for (int i = 0; i < 25; ++i) wr[i] = *(const ull*)&wsh[i*64 + 2*dp];
    const ull bias2 = *(const ull*)(bias + 2*dp);

    const int y0 = yt*TY;

    auto loadrow = [&](int y){
        const int s = (y + 10) % 5;
        float* dst = ring + (size_t)s*68*64;
        if (y < 0 || y >= HT){
            #pragma unroll
            for (int k2 = 0; k2 < 4; ++k2){
                int f = t + k2*256;
                int x = f >> 4, dq = f & 15;
                *(float4*)&dst[(x+2)*64 + dq*4] = make_float4(0.f,0.f,0.f,0.f);
            }
        } else {
            const float* src = vin + ((size_t)(n*LL + y*WD)*HH + h)*DD;
            #pragma unroll
            for (int k2 = 0; k2 < 4; ++k2){
                int f = t + k2*256;
                int x = f >> 4, dq = f & 15;
                *(float4*)&dst[(x+2)*64 + dq*4] =
                    *(const float4*)&src[(size_t)x*ROWSTRIDE + dq*4];
            }
        }
    };

    loadrow(y0-2); loadrow(y0-1); loadrow(y0); loadrow(y0+1);

    for (int yo = 0; yo < TY; ++yo){
        const int y = y0 + yo;
        loadrow(y+2);
        __syncthreads();

        ull acc[8];
        #pragma unroll
        for (int xx = 0; xx < 8; ++xx) acc[xx] = bias2;
        const int x0 = xg*8;

        #pragma unroll
        for (int dy = 0; dy < 5; ++dy){
            const int s = (y + dy + 8) % 5;
            const float* rp = ring + (size_t)s*68*64 + 2*dp;
            ull win[12];
            #pragma unroll
            for (int i = 0; i < 12; ++i) win[i] = *(const ull*)&rp[(x0+i)*64];
            #pragma unroll
            for (int xx = 0; xx < 8; ++xx)
                #pragma unroll
                for (int dx = 0; dx < 5; ++dx)
                    ffma2(acc[xx], wr[dy*5+dx], win[xx+dx]);
        }

        float* ob = out + ((size_t)(n*LL + y*WD + x0)*HH + h)*DD + 2*dp;
        #pragma unroll
        for (int xx = 0; xx < 8; ++xx)
            *(ull*)(ob + (size_t)xx*ROWSTRIDE) = acc[xx];
        __syncthreads();
    }
}

// ---------------- launch (fork-join: conv overlaps kv+reduce) ----------------
extern "C" void kernel_launch(void* const* d_in, const int* in_sizes, int n_in,
                              void* d_out, int out_size){
    const float* q  = (const float*)d_in[0];
    const float* k  = (const float*)d_in[1];
    const float* v  = (const float*)d_in[2];
    const float* sp = (const float*)d_in[3];
    const float* w  = (const float*)d_in[4];
    const float* b  = (const float*)d_in[5];
    float* out = (float*)d_out;

    static cudaStream_t s2 = nullptr;
    static cudaEvent_t evFork = nullptr, evJoin = nullptr;
    if (!s2){
        cudaStreamCreateWithFlags(&s2, cudaStreamNonBlocking);
        cudaEventCreateWithFlags(&evFork, cudaEventDisableTiming);
        cudaEventCreateWithFlags(&evJoin, cudaEventDisableTiming);
        cudaFuncSetAttribute(k_kv,   cudaFuncAttributeMaxDynamicSharedMemorySize, KV_SMEM);
        cudaFuncSetAttribute(k_attn, cudaFuncAttributeMaxDynamicSharedMemorySize, ATTN_SMEM);
        cudaFuncSetAttribute(k_conv, cudaFuncAttributeMaxDynamicSharedMemorySize, K3_SMEM_FLOATS*4);
    }

    // fork: conv (writes out = conv+bias) runs concurrently with kv pipeline
    cudaEventRecord(evFork, 0);
    cudaStreamWaitEvent(s2, evFork, 0);
    k_conv<<<NHH*(HT/TY), 256, K3_SMEM_FLOATS*4, s2>>>(v, w, b, out);
    cudaEventRecord(evJoin, s2);

    k_kv<<<NHH*CHUNKS, 64, KV_SMEM>>>(k, v, sp);
    k_kvreduce<<<512, 128>>>();

    // join: attn RMW-adds attention onto conv output
    cudaStreamWaitEvent(0, evJoin, 0);
    k_attn<<<NHH*(LL/TILE_L), 128, ATTN_SMEM>>>(q, sp, out);
}